// round 10
// baseline (speedup 1.0000x reference)
#include <cuda_runtime.h>
#include <cuda_fp16.h>
#include <math.h>

// Problem constants
#define NVOX 32768          // 32*32*32 voxels
#define NC   64             // channels
#define DP2  36             // padded dim + extra zero ring
#define GC   32             // channels per group
#define NG   2              // groups
#define NP   27             // kernel points
#define NOFF 162            // G*P*3
#define NMSK 54             // G*P
#define NJP  320            // padded j rows: 64 inp | 162 off | 54 mask | 40 zero
#define HVOL  (DP2*DP2*DP2*GC)  // halves per group = 1492992
#define HVOL4 (HVOL/8)          // float4 (8 halves) per group = 186624
#define KDW_BLOCKS 2048

typedef unsigned long long u64;

// packed fp32x2 helpers (sm_103a FFMA2 via PTX)
__device__ __forceinline__ u64 pk2(float lo, float hi) {
    u64 r; asm("mov.b64 %0, {%1, %2};" : "=l"(r) : "f"(lo), "f"(hi)); return r;
}
__device__ __forceinline__ void fma2(u64& d, u64 a, u64 b) {
    asm("fma.rn.f32x2 %0, %1, %2, %0;" : "+l"(d) : "l"(a), "l"(b));
}
__device__ __forceinline__ float2 upk2(u64 v) {
    float2 f; asm("mov.b64 {%0, %1}, %2;" : "=f"(f.x), "=f"(f.y) : "l"(v)); return f;
}

// ---- scratch (static device globals; zero-initialized at module load) ----
__device__ __align__(256) float  g_xc[NC*NVOX];     // depthwise conv out, c-major [c][v]
__device__ __align__(256) __half g_xph[NG*HVOL];    // fp16 ring-padded projected volume
__device__ __align__(256) float  g_off[NOFF*NVOX];  // offsets, transposed [j][v]
__device__ __align__(256) float  g_mask[NMSK*NVOX]; // mask logits, transposed [j][v]
__device__ __align__(256) float  g_samp[NC*NVOX];   // sampled+masked result, c-major [c][v]
__device__ float g_part[KDW_BLOCKS*2];
__device__ float g_stats[2];
__device__ __align__(256) float g_wtT[NC*NJP];      // weights [k][j], j-reordered+padded
__device__ float g_bias[NJP];

// ---------------------------------------------------------------------------
// Kernel 0: build reordered weight matrix [k][j] + bias
// ---------------------------------------------------------------------------
__global__ void k_init(const float* __restrict__ inp_w, const float* __restrict__ off_w,
                       const float* __restrict__ mask_w,
                       const float* __restrict__ inp_b, const float* __restrict__ off_b,
                       const float* __restrict__ mask_b) {
    int gid = blockIdx.x * 256 + threadIdx.x;
    if (gid < NC * NJP) {
        int k = gid / NJP, j = gid - k * NJP;
        float v = 0.f;
        if (j < 64)       v = inp_w[k * NC + j];
        else if (j < 226) v = off_w[k * NOFF + (j - 64)];
        else if (j < 280) v = mask_w[k * NMSK + (j - 226)];
        g_wtT[gid] = v;
    }
    if (gid < NJP) {
        int j = gid;
        float b = 0.f;
        if (j < 64)       b = inp_b[j];
        else if (j < 226) b = off_b[j - 64];
        else if (j < 280) b = mask_b[j - 226];
        g_bias[j] = b;
    }
}

// ---------------------------------------------------------------------------
// Kernel 1: depthwise 3x3x3 conv via smem slab (3 z-slices + halo).
// ---------------------------------------------------------------------------
__global__ void k_dw(const float* __restrict__ x, const float* __restrict__ dw_w) {
    int bz = blockIdx.x, c = blockIdx.y;
    int tid = threadIdx.x;
    __shared__ float s[3][34][34];
    __shared__ float sh[8][2];

    const float* xs = x + c * NVOX;
    for (int i = tid; i < 3 * 34 * 34; i += 256) {
        int sl = i / 1156;
        int rem = i - sl * 1156;
        int yy = rem / 34;
        int xx = rem - yy * 34;
        int z = bz + sl - 1, y = yy - 1, xg = xx - 1;
        float val = 0.f;
        if ((unsigned)z < 32u && (unsigned)y < 32u && (unsigned)xg < 32u)
            val = xs[(z << 10) + (y << 5) + xg];
        s[sl][yy][xx] = val;
    }
    float w[27];
#pragma unroll
    for (int k = 0; k < 27; k++) w[k] = __ldg(dw_w + c * 27 + k);
    __syncthreads();

    float ls = 0.f, ls2 = 0.f;
#pragma unroll
    for (int q = 0; q < 4; q++) {
        int vloc = q * 256 + tid;
        int iy = vloc >> 5, ix = vloc & 31;
        float acc = 0.f;
#pragma unroll
        for (int kz = 0; kz < 3; kz++)
#pragma unroll
            for (int ky = 0; ky < 3; ky++)
#pragma unroll
                for (int kx = 0; kx < 3; kx++)
                    acc = fmaf(w[kz*9 + ky*3 + kx], s[kz][iy + ky][ix + kx], acc);
        g_xc[c * NVOX + (bz << 10) + vloc] = acc;
        ls += acc; ls2 += acc * acc;
    }

#pragma unroll
    for (int o = 16; o > 0; o >>= 1) {
        ls  += __shfl_down_sync(0xffffffffu, ls,  o);
        ls2 += __shfl_down_sync(0xffffffffu, ls2, o);
    }
    int lane = tid & 31, warp = tid >> 5;
    if (lane == 0) { sh[warp][0] = ls; sh[warp][1] = ls2; }
    __syncthreads();
    if (tid == 0) {
        float S = 0.f, S2 = 0.f;
#pragma unroll
        for (int i = 0; i < 8; i++) { S += sh[i][0]; S2 += sh[i][1]; }
        int bid = c * 32 + bz;
        g_part[bid * 2]     = S;
        g_part[bid * 2 + 1] = S2;
    }
}

// ---------------------------------------------------------------------------
// Kernel 2: finalize mean / rstd
// ---------------------------------------------------------------------------
__global__ void k_stats() {
    int tid = threadIdx.x;
    float s = 0.f, s2 = 0.f;
    for (int i = tid; i < KDW_BLOCKS; i += 1024) {
        float2 p = reinterpret_cast<const float2*>(g_part)[i];
        s += p.x; s2 += p.y;
    }
#pragma unroll
    for (int o = 16; o > 0; o >>= 1) {
        s  += __shfl_down_sync(0xffffffffu, s,  o);
        s2 += __shfl_down_sync(0xffffffffu, s2, o);
    }
    __shared__ float sh[32][2];
    int lane = tid & 31, wid = tid >> 5;
    if (lane == 0) { sh[wid][0] = s; sh[wid][1] = s2; }
    __syncthreads();
    if (tid == 0) {
        float S = 0.f, S2 = 0.f;
#pragma unroll
        for (int i = 0; i < 32; i++) { S += sh[i][0]; S2 += sh[i][1]; }
        float n   = (float)(NVOX * NC);
        float mu  = S / n;
        float var = S2 / n - mu * mu;
        g_stats[0] = mu;
        g_stats[1] = rsqrtf(var + 1e-5f);
    }
}

// ---------------------------------------------------------------------------
// Kernel 3: tiled GEMM with packed f32x2 FMA. C[v][j] = A[v][k]*W[k][j].
// M=32768, N=320, K=64. grid (256, 5), 128 threads, thread tile 8v x 8j,
// accumulators = 4 voxel-pairs x 8 j in f32x2.
// ---------------------------------------------------------------------------
__global__ void __launch_bounds__(128)
k_point(const float* __restrict__ x,
        const float* __restrict__ gn_w, const float* __restrict__ gn_b) {
    int jt = blockIdx.y;
    int vbase = blockIdx.x * 128;
    int tid = threadIdx.x;
    __shared__ float sA[64 * 128];
    __shared__ float sB[64 * 64];

    // stage B: 1024 float4, 8 per thread
#pragma unroll
    for (int i = 0; i < 8; i++) {
        int lin = i * 128 + tid;             // float4 index
        int k = lin >> 4, j4 = lin & 15;
        reinterpret_cast<float4*>(sB)[lin] =
            *reinterpret_cast<const float4*>(&g_wtT[k * NJP + jt * 64 + j4 * 4]);
    }
    // stage A: 2048 float4, 16 per thread
    if (jt == 0) {
#pragma unroll
        for (int i = 0; i < 16; i++) {
            int lin = i * 128 + tid;
            int k = lin >> 5, v4 = lin & 31;
            reinterpret_cast<float4*>(sA)[lin] =
                *reinterpret_cast<const float4*>(&x[k * NVOX + vbase + v4 * 4]);
        }
    } else {
        float mu = g_stats[0], rstd = g_stats[1];
#pragma unroll
        for (int i = 0; i < 16; i++) {
            int lin = i * 128 + tid;
            int k = lin >> 5, v4 = lin & 31;
            float gw = __ldg(gn_w + k) * rstd;
            float gb = __ldg(gn_b + k) - mu * gw;
            float4 xv = *reinterpret_cast<const float4*>(&g_xc[k * NVOX + vbase + v4 * 4]);
            float r[4] = {xv.x, xv.y, xv.z, xv.w};
#pragma unroll
            for (int e = 0; e < 4; e++) {
                float xn = r[e] * gw + gb;
                float u = xn + 0.044715f * xn * xn * xn;
                r[e] = xn / (1.f + __expf(-1.5957691216057308f * u));
            }
            reinterpret_cast<float4*>(sA)[lin] = make_float4(r[0], r[1], r[2], r[3]);
        }
    }
    __syncthreads();

    int tx = tid & 15, ty = tid >> 4;        // tx: voxel octet, ty: j octet
    u64 acc2[4][8];
#pragma unroll
    for (int i = 0; i < 4; i++)
#pragma unroll
        for (int j = 0; j < 8; j++) acc2[i][j] = 0ull;

    const float4* A4 = reinterpret_cast<const float4*>(sA);
    const float4* B4 = reinterpret_cast<const float4*>(sB);
#pragma unroll 4
    for (int k = 0; k < 64; k++) {
        float4 a0 = A4[k * 32 + tx * 2];
        float4 a1 = A4[k * 32 + tx * 2 + 1];
        float4 b0 = B4[k * 16 + ty * 2];
        float4 b1 = B4[k * 16 + ty * 2 + 1];
        u64 av[4] = {pk2(a0.x, a0.y), pk2(a0.z, a0.w),
                     pk2(a1.x, a1.y), pk2(a1.z, a1.w)};
        u64 bb[8] = {pk2(b0.x, b0.x), pk2(b0.y, b0.y), pk2(b0.z, b0.z), pk2(b0.w, b0.w),
                     pk2(b1.x, b1.x), pk2(b1.y, b1.y), pk2(b1.z, b1.z), pk2(b1.w, b1.w)};
#pragma unroll
        for (int pv = 0; pv < 4; pv++)
#pragma unroll
            for (int jj = 0; jj < 8; jj++)
                fma2(acc2[pv][jj], av[pv], bb[jj]);
    }

    // unpack
    float accv[8][8];
#pragma unroll
    for (int pv = 0; pv < 4; pv++)
#pragma unroll
        for (int jj = 0; jj < 8; jj++) {
            float2 f = upk2(acc2[pv][jj]);
            accv[2 * pv][jj] = f.x;
            accv[2 * pv + 1][jj] = f.y;
        }

    if (jt == 0) {
        // j = output channels ty*8..+7 of input projection -> fp16 volume
        int g = ty >> 2;
        int ch = (ty & 3) * 8;
        float4 b40 = *reinterpret_cast<const float4*>(&g_bias[ty * 8]);
        float4 b41 = *reinterpret_cast<const float4*>(&g_bias[ty * 8 + 4]);
#pragma unroll
        for (int vi = 0; vi < 8; vi++) {
            int v = vbase + tx * 8 + vi;
            int iz = v >> 10, iy = (v >> 5) & 31, ix = v & 31;
            int pos = (((g * DP2 + iz + 2) * DP2 + iy + 2) * DP2 + ix + 2);
            __half2 h0 = __floats2half2_rn(accv[vi][0] + b40.x, accv[vi][1] + b40.y);
            __half2 h1 = __floats2half2_rn(accv[vi][2] + b40.z, accv[vi][3] + b40.w);
            __half2 h2 = __floats2half2_rn(accv[vi][4] + b41.x, accv[vi][5] + b41.y);
            __half2 h3 = __floats2half2_rn(accv[vi][6] + b41.z, accv[vi][7] + b41.w);
            uint4 u;
            u.x = *reinterpret_cast<unsigned*>(&h0);
            u.y = *reinterpret_cast<unsigned*>(&h1);
            u.z = *reinterpret_cast<unsigned*>(&h2);
            u.w = *reinterpret_cast<unsigned*>(&h3);
            *reinterpret_cast<uint4*>(&g_xph[(pos << 5) + ch]) = u;
        }
    } else {
#pragma unroll
        for (int jj = 0; jj < 8; jj++) {
            int j = jt * 64 + ty * 8 + jj;
            float* dst;
            if (j < 226)      dst = g_off  + (j - 64)  * NVOX;
            else if (j < 280) dst = g_mask + (j - 226) * NVOX;
            else continue;
            float bj = g_bias[j];
            *reinterpret_cast<float4*>(dst + vbase + tx * 8) =
                make_float4(accv[0][jj] + bj, accv[1][jj] + bj,
                            accv[2][jj] + bj, accv[3][jj] + bj);
            *reinterpret_cast<float4*>(dst + vbase + tx * 8 + 4) =
                make_float4(accv[4][jj] + bj, accv[5][jj] + bj,
                            accv[6][jj] + bj, accv[7][jj] + bj);
        }
    }
}

// ---------------------------------------------------------------------------
// Kernel 4: deformable trilinear sampling (fp16 volume), x-paired taps.
// Block = 4x4x2 voxel tile x ONE group; 256 threads = 32 vox x 8 lanes.
// Lane: xsel = bit2 picks the x0/x1 corner column, c4 = bits[0:1] picks
// 8 channels (one float4 of halves). Per point: 4 zy-corner loads/lane;
// the 8 lanes of a voxel cover a contiguous 128B x-pair span.
// xsel partials merged by one shfl_xor(4) per channel at the end.
// ---------------------------------------------------------------------------
__global__ void __launch_bounds__(256) k_samp() {
    int bid = blockIdx.x;            // 2048 = 1024 tiles x 2 groups
    int gi = bid & 1;
    int tile = bid >> 1;
    int tbx = tile & 7, tby = (tile >> 3) & 7, tbz = tile >> 6;   // z tiles: 16
    int tid = threadIdx.x;

    __shared__ float s_off[32][81];
    __shared__ float s_m[32][28];

    for (int idx = tid; idx < 32 * 81; idx += 256) {
        int j = idx >> 5, vl = idx & 31;
        int vx = tbx * 4 + (vl & 3), vy = tby * 4 + ((vl >> 2) & 3), vz = tbz * 2 + (vl >> 4);
        s_off[vl][j] = g_off[(gi * 81 + j) * NVOX + (vz << 10) + (vy << 5) + vx];
    }
    for (int idx = tid; idx < 32 * 27; idx += 256) {
        int j = idx >> 5, vl = idx & 31;
        int vx = tbx * 4 + (vl & 3), vy = tby * 4 + ((vl >> 2) & 3), vz = tbz * 2 + (vl >> 4);
        s_m[vl][j] = g_mask[(gi * 27 + j) * NVOX + (vz << 10) + (vy << 5) + vx];
    }
    __syncthreads();

    // softmax over 27 points, one thread per voxel
    if (tid < 32) {
        float* m = s_m[tid];
        float mx = -1e30f;
#pragma unroll
        for (int p = 0; p < NP; p++) mx = fmaxf(mx, m[p]);
        float s = 0.f;
#pragma unroll
        for (int p = 0; p < NP; p++) { float e = __expf(m[p] - mx); m[p] = e; s += e; }
        float inv = 1.f / s;
#pragma unroll
        for (int p = 0; p < NP; p++) m[p] *= inv;
    }
    __syncthreads();

    int vv = tid >> 3;               // local voxel 0..31
    int lane8 = tid & 7;
    int xsel = lane8 >> 2;           // 0: x0 corner, 1: x1 corner
    int c4 = lane8 & 3;              // 8 channels via float4 of halves
    int ix = tbx * 4 + (vv & 3);
    int iy = tby * 4 + ((vv >> 2) & 3);
    int iz = tbz * 2 + (vv >> 4);

    const float4* vol4 = reinterpret_cast<const float4*>(g_xph) + gi * HVOL4 + c4;
    const float* offp = s_off[vv];
    const float* mp   = s_m[vv];

    float acc[8];
#pragma unroll
    for (int e = 0; e < 8; e++) acc[e] = 0.f;

    int kx = 0, ky = 0, kz = 0;
#pragma unroll 1
    for (int p = 0; p < NP; p++) {
        float ox = offp[p * 3 + 0];
        float oy = offp[p * 3 + 1];
        float oz = offp[p * 3 + 2];
        float sx = (float)(ix + kx + 1) + 0.25f * ox;
        float sy = (float)(iy + ky + 1) + 0.5f  * oy;
        float sz = (float)(iz + kz + 1) + 0.5f  * oz;
        if (++kx == 3) { kx = 0; if (++ky == 3) { ky = 0; ++kz; } }

        float xf = floorf(sx), yf = floorf(sy), zf = floorf(sz);
        float fx = sx - xf, fy = sy - yf, fz = sz - zf;
        int x0 = (int)xf, y0 = (int)yf, z0 = (int)zf;
        int xc  = min(max(x0 + xsel, 0), DP2 - 1);
        int y0c = min(max(y0, 0), DP2 - 1),     z0c = min(max(z0, 0), DP2 - 1);
        int y1c = min(max(y0 + 1, 0), DP2 - 1), z1c = min(max(z0 + 1, 0), DP2 - 1);

        int i00 = ((z0c * DP2 + y0c) * DP2 + xc) << 2;
        int i01 = ((z0c * DP2 + y1c) * DP2 + xc) << 2;
        int i10 = ((z1c * DP2 + y0c) * DP2 + xc) << 2;
        int i11 = ((z1c * DP2 + y1c) * DP2 + xc) << 2;

        float4 t00 = vol4[i00];
        float4 t01 = vol4[i01];
        float4 t10 = vol4[i10];
        float4 t11 = vol4[i11];

        float wxm = mp[p] * (xsel ? fx : 1.f - fx);
        float gy1 = fy, gy0 = 1.f - fy;
        float gz1 = fz, gz0 = 1.f - fz;
        float w00 = gz0 * gy0 * wxm, w01 = gz0 * gy1 * wxm;
        float w10 = gz1 * gy0 * wxm, w11 = gz1 * gy1 * wxm;

#define TAP(T, W) { \
        const __half2* hh = reinterpret_cast<const __half2*>(&T); \
        float2 f0 = __half22float2(hh[0]); \
        float2 f1 = __half22float2(hh[1]); \
        float2 f2 = __half22float2(hh[2]); \
        float2 f3 = __half22float2(hh[3]); \
        acc[0] = fmaf(W, f0.x, acc[0]); acc[1] = fmaf(W, f0.y, acc[1]); \
        acc[2] = fmaf(W, f1.x, acc[2]); acc[3] = fmaf(W, f1.y, acc[3]); \
        acc[4] = fmaf(W, f2.x, acc[4]); acc[5] = fmaf(W, f2.y, acc[5]); \
        acc[6] = fmaf(W, f3.x, acc[6]); acc[7] = fmaf(W, f3.y, acc[7]); }
        TAP(t00, w00) TAP(t01, w01) TAP(t10, w10) TAP(t11, w11)
#undef TAP
    }

    // merge x0/x1 partials (partner lane differs in bit 2)
#pragma unroll
    for (int e = 0; e < 8; e++)
        acc[e] += __shfl_xor_sync(0xffffffffu, acc[e], 4);

    // each lane stores its half of the 8 channels, c-major [c][v]
    int v = (iz << 10) + (iy << 5) + ix;
    int cb = gi * GC + c4 * 8 + xsel * 4;
#pragma unroll
    for (int e = 0; e < 4; e++)
        g_samp[(cb + e) * NVOX + v] = acc[xsel * 4 + e];
}

// ---------------------------------------------------------------------------
// Kernel 5: output GEMM. out[v][oc] = g_samp[c][v]^T @ out_w[c][oc] + out_b.
// ---------------------------------------------------------------------------
__global__ void __launch_bounds__(256)
k_out(const float* __restrict__ out_w, const float* __restrict__ out_b,
      float* __restrict__ out) {
    int vbase = blockIdx.x * 128;
    int tid = threadIdx.x;
    __shared__ float sA[64 * 128];
    __shared__ float sB[64 * 64];

#pragma unroll
    for (int i = 0; i < 4; i++) {
        int lin = i * 1024 + tid * 4;
        *reinterpret_cast<float4*>(&sB[lin]) =
            *reinterpret_cast<const float4*>(&out_w[lin]);
    }
#pragma unroll
    for (int i = 0; i < 8; i++) {
        int lin = i * 1024 + tid * 4;
        int k = lin >> 7, vl = lin & 127;
        *reinterpret_cast<float4*>(&sA[lin]) =
            *reinterpret_cast<const float4*>(&g_samp[k * NVOX + vbase + vl]);
    }
    __syncthreads();

    int tx = tid & 15, ty = tid >> 4;
    float acc[8][4];
#pragma unroll
    for (int i = 0; i < 8; i++)
#pragma unroll
        for (int j = 0; j < 4; j++) acc[i][j] = 0.f;

    const float4* A4 = reinterpret_cast<const float4*>(sA);
    const float4* B4 = reinterpret_cast<const float4*>(sB);
#pragma unroll 8
    for (int k = 0; k < 64; k++) {
        float4 a0 = A4[k * 32 + tx];
        float4 a1 = A4[k * 32 + 16 + tx];
        float4 b  = B4[k * 16 + ty];
        float av[8] = {a0.x, a0.y, a0.z, a0.w, a1.x, a1.y, a1.z, a1.w};
        float bv[4] = {b.x, b.y, b.z, b.w};
#pragma unroll
        for (int i = 0; i < 8; i++)
#pragma unroll
            for (int j = 0; j < 4; j++)
                acc[i][j] = fmaf(av[i], bv[j], acc[i][j]);
    }

    float4 b4 = *reinterpret_cast<const float4*>(&out_b[ty * 4]);
#pragma unroll
    for (int vi = 0; vi < 8; vi++) {
        int v = vbase + ((vi & 4) << 4) + tx * 4 + (vi & 3);
        *reinterpret_cast<float4*>(&out[v * NC + ty * 4]) =
            make_float4(acc[vi][0] + b4.x, acc[vi][1] + b4.y,
                        acc[vi][2] + b4.z, acc[vi][3] + b4.w);
    }
}

// ---------------------------------------------------------------------------
extern "C" void kernel_launch(void* const* d_in, const int* in_sizes, int n_in,
                              void* d_out, int out_size) {
    const float* x      = (const float*)d_in[0];
    const float* dw_w   = (const float*)d_in[1];
    const float* gn_w   = (const float*)d_in[2];
    const float* gn_b   = (const float*)d_in[3];
    const float* inp_w  = (const float*)d_in[4];
    const float* inp_b  = (const float*)d_in[5];
    const float* off_w  = (const float*)d_in[6];
    const float* off_b  = (const float*)d_in[7];
    const float* mask_w = (const float*)d_in[8];
    const float* mask_b = (const float*)d_in[9];
    const float* out_w  = (const float*)d_in[10];
    const float* out_b  = (const float*)d_in[11];
    float* out = (float*)d_out;

    k_init<<<(NC * NJP + 255) / 256, 256>>>(inp_w, off_w, mask_w, inp_b, off_b, mask_b);
    k_dw<<<dim3(32, 64), 256>>>(x, dw_w);
    k_stats<<<1, 1024>>>();
    k_point<<<dim3(NVOX / 128, 5), 128>>>(x, gn_w, gn_b);
    k_samp<<<2048, 256>>>();
    k_out<<<NVOX / 128, 256>>>(out_w, out_b, out);
}

// round 11
// speedup vs baseline: 1.1366x; 1.1366x over previous
#include <cuda_runtime.h>
#include <cuda_fp16.h>
#include <math.h>

// Problem constants
#define NVOX 32768          // 32*32*32 voxels
#define NC   64             // channels
#define DP2  36             // padded dim + extra zero ring
#define GC   32             // channels per group
#define NG   2              // groups
#define NP   27             // kernel points
#define NOFF 162            // G*P*3
#define NMSK 54             // G*P
#define NJP  320            // padded j rows: 64 inp | 162 off | 54 mask | 40 zero
#define HVOL  (DP2*DP2*DP2*GC)  // halves per group = 1492992
#define HVOL4 (HVOL/8)          // float4 (8 halves) per group
#define KDW_BLOCKS 2048

// ---- scratch (static device globals; zero-initialized at module load) ----
__device__ __align__(256) float  g_xc[NC*NVOX];     // depthwise conv out, c-major [c][v]
__device__ __align__(256) __half g_xph[NG*HVOL];    // fp16 ring-padded projected volume
__device__ __align__(256) float  g_off[NOFF*NVOX];  // offsets, transposed [j][v]
__device__ __align__(256) float  g_mask[NMSK*NVOX]; // mask logits, transposed [j][v]
__device__ __align__(256) float  g_samp[NC*NVOX];   // sampled+masked result, c-major [c][v]
__device__ float g_part[KDW_BLOCKS*2];
__device__ float g_stats[2];
__device__ __align__(256) float g_wtT[NC*NJP];      // weights [k][j], j-reordered+padded
__device__ float g_bias[NJP];

// ---------------------------------------------------------------------------
// Kernel 0: build reordered weight matrix [k][j] + bias
// ---------------------------------------------------------------------------
__global__ void k_init(const float* __restrict__ inp_w, const float* __restrict__ off_w,
                       const float* __restrict__ mask_w,
                       const float* __restrict__ inp_b, const float* __restrict__ off_b,
                       const float* __restrict__ mask_b) {
    int gid = blockIdx.x * 256 + threadIdx.x;
    if (gid < NC * NJP) {
        int k = gid / NJP, j = gid - k * NJP;
        float v = 0.f;
        if (j < 64)       v = inp_w[k * NC + j];
        else if (j < 226) v = off_w[k * NOFF + (j - 64)];
        else if (j < 280) v = mask_w[k * NMSK + (j - 226)];
        g_wtT[gid] = v;
    }
    if (gid < NJP) {
        int j = gid;
        float b = 0.f;
        if (j < 64)       b = inp_b[j];
        else if (j < 226) b = off_b[j - 64];
        else if (j < 280) b = mask_b[j - 226];
        g_bias[j] = b;
    }
}

// ---------------------------------------------------------------------------
// Kernel 1: depthwise 3x3x3 conv via smem slab (3 z-slices + halo).
// ---------------------------------------------------------------------------
__global__ void k_dw(const float* __restrict__ x, const float* __restrict__ dw_w) {
    int bz = blockIdx.x, c = blockIdx.y;
    int tid = threadIdx.x;
    __shared__ float s[3][34][34];
    __shared__ float sh[8][2];

    const float* xs = x + c * NVOX;
    for (int i = tid; i < 3 * 34 * 34; i += 256) {
        int sl = i / 1156;
        int rem = i - sl * 1156;
        int yy = rem / 34;
        int xx = rem - yy * 34;
        int z = bz + sl - 1, y = yy - 1, xg = xx - 1;
        float val = 0.f;
        if ((unsigned)z < 32u && (unsigned)y < 32u && (unsigned)xg < 32u)
            val = xs[(z << 10) + (y << 5) + xg];
        s[sl][yy][xx] = val;
    }
    float w[27];
#pragma unroll
    for (int k = 0; k < 27; k++) w[k] = __ldg(dw_w + c * 27 + k);
    __syncthreads();

    float ls = 0.f, ls2 = 0.f;
#pragma unroll
    for (int q = 0; q < 4; q++) {
        int vloc = q * 256 + tid;
        int iy = vloc >> 5, ix = vloc & 31;
        float acc = 0.f;
#pragma unroll
        for (int kz = 0; kz < 3; kz++)
#pragma unroll
            for (int ky = 0; ky < 3; ky++)
#pragma unroll
                for (int kx = 0; kx < 3; kx++)
                    acc = fmaf(w[kz*9 + ky*3 + kx], s[kz][iy + ky][ix + kx], acc);
        g_xc[c * NVOX + (bz << 10) + vloc] = acc;
        ls += acc; ls2 += acc * acc;
    }

#pragma unroll
    for (int o = 16; o > 0; o >>= 1) {
        ls  += __shfl_down_sync(0xffffffffu, ls,  o);
        ls2 += __shfl_down_sync(0xffffffffu, ls2, o);
    }
    int lane = tid & 31, warp = tid >> 5;
    if (lane == 0) { sh[warp][0] = ls; sh[warp][1] = ls2; }
    __syncthreads();
    if (tid == 0) {
        float S = 0.f, S2 = 0.f;
#pragma unroll
        for (int i = 0; i < 8; i++) { S += sh[i][0]; S2 += sh[i][1]; }
        int bid = c * 32 + bz;
        g_part[bid * 2]     = S;
        g_part[bid * 2 + 1] = S2;
    }
}

// ---------------------------------------------------------------------------
// Kernel 2: finalize mean / rstd
// ---------------------------------------------------------------------------
__global__ void k_stats() {
    int tid = threadIdx.x;
    float s = 0.f, s2 = 0.f;
    for (int i = tid; i < KDW_BLOCKS; i += 1024) {
        float2 p = reinterpret_cast<const float2*>(g_part)[i];
        s += p.x; s2 += p.y;
    }
#pragma unroll
    for (int o = 16; o > 0; o >>= 1) {
        s  += __shfl_down_sync(0xffffffffu, s,  o);
        s2 += __shfl_down_sync(0xffffffffu, s2, o);
    }
    __shared__ float sh[32][2];
    int lane = tid & 31, wid = tid >> 5;
    if (lane == 0) { sh[wid][0] = s; sh[wid][1] = s2; }
    __syncthreads();
    if (tid == 0) {
        float S = 0.f, S2 = 0.f;
#pragma unroll
        for (int i = 0; i < 32; i++) { S += sh[i][0]; S2 += sh[i][1]; }
        float n   = (float)(NVOX * NC);
        float mu  = S / n;
        float var = S2 / n - mu * mu;
        g_stats[0] = mu;
        g_stats[1] = rsqrtf(var + 1e-5f);
    }
}

// ---------------------------------------------------------------------------
// Kernel 3: tiled GEMM (R9-proven form). C[v][j] = A[v][k] * W[k][j].
// grid (256, 5), 256 threads, thread tile 8v x 4j.
// ---------------------------------------------------------------------------
__global__ void __launch_bounds__(256)
k_point(const float* __restrict__ x,
        const float* __restrict__ gn_w, const float* __restrict__ gn_b) {
    int jt = blockIdx.y;
    int vbase = blockIdx.x * 128;
    int tid = threadIdx.x;
    __shared__ float sA[64 * 128];
    __shared__ float sB[64 * 64];

#pragma unroll
    for (int i = 0; i < 4; i++) {
        int lin = i * 1024 + tid * 4;
        int k = lin >> 6, j = lin & 63;
        *reinterpret_cast<float4*>(&sB[lin]) =
            *reinterpret_cast<const float4*>(&g_wtT[k * NJP + jt * 64 + j]);
    }
    if (jt == 0) {
#pragma unroll
        for (int i = 0; i < 8; i++) {
            int lin = i * 1024 + tid * 4;
            int k = lin >> 7, vl = lin & 127;
            *reinterpret_cast<float4*>(&sA[lin]) =
                *reinterpret_cast<const float4*>(&x[k * NVOX + vbase + vl]);
        }
    } else {
        float mu = g_stats[0], rstd = g_stats[1];
#pragma unroll
        for (int i = 0; i < 8; i++) {
            int lin = i * 1024 + tid * 4;
            int k = lin >> 7, vl = lin & 127;
            float gw = __ldg(gn_w + k) * rstd;
            float gb = __ldg(gn_b + k) - mu * gw;
            float4 xv = *reinterpret_cast<const float4*>(&g_xc[k * NVOX + vbase + vl]);
            float r[4] = {xv.x, xv.y, xv.z, xv.w};
#pragma unroll
            for (int e = 0; e < 4; e++) {
                float xn = r[e] * gw + gb;
                float u = xn + 0.044715f * xn * xn * xn;
                r[e] = xn / (1.f + __expf(-1.5957691216057308f * u));
            }
            *reinterpret_cast<float4*>(&sA[lin]) = make_float4(r[0], r[1], r[2], r[3]);
        }
    }
    __syncthreads();

    int tx = tid & 15, ty = tid >> 4;
    float acc[8][4];
#pragma unroll
    for (int i = 0; i < 8; i++)
#pragma unroll
        for (int j = 0; j < 4; j++) acc[i][j] = 0.f;

    const float4* A4 = reinterpret_cast<const float4*>(sA);
    const float4* B4 = reinterpret_cast<const float4*>(sB);
#pragma unroll 8
    for (int k = 0; k < 64; k++) {
        float4 a0 = A4[k * 32 + tx];
        float4 a1 = A4[k * 32 + 16 + tx];
        float4 b  = B4[k * 16 + ty];
        float av[8] = {a0.x, a0.y, a0.z, a0.w, a1.x, a1.y, a1.z, a1.w};
        float bv[4] = {b.x, b.y, b.z, b.w};
#pragma unroll
        for (int i = 0; i < 8; i++)
#pragma unroll
            for (int j = 0; j < 4; j++)
                acc[i][j] = fmaf(av[i], bv[j], acc[i][j]);
    }

    if (jt == 0) {
        int o = ty * 4;
        int g = o >> 5, ch = o & 31;
        float4 b4 = *reinterpret_cast<const float4*>(&g_bias[o]);
#pragma unroll
        for (int vi = 0; vi < 8; vi++) {
            int v = vbase + ((vi & 4) << 4) + tx * 4 + (vi & 3);
            int iz = v >> 10, iy = (v >> 5) & 31, ix = v & 31;
            int pos = (((g * DP2 + iz + 2) * DP2 + iy + 2) * DP2 + ix + 2);
            __half2 h01 = __floats2half2_rn(acc[vi][0] + b4.x, acc[vi][1] + b4.y);
            __half2 h23 = __floats2half2_rn(acc[vi][2] + b4.z, acc[vi][3] + b4.w);
            uint2 u;
            u.x = *reinterpret_cast<unsigned*>(&h01);
            u.y = *reinterpret_cast<unsigned*>(&h23);
            *reinterpret_cast<uint2*>(&g_xph[(pos << 5) + ch]) = u;
        }
    } else {
#pragma unroll
        for (int jj = 0; jj < 4; jj++) {
            int j = jt * 64 + ty * 4 + jj;
            float* dst;
            if (j < 226)      dst = g_off  + (j - 64)  * NVOX;
            else if (j < 280) dst = g_mask + (j - 226) * NVOX;
            else continue;
            float bj = g_bias[j];
            *reinterpret_cast<float4*>(dst + vbase + tx * 4) =
                make_float4(acc[0][jj] + bj, acc[1][jj] + bj,
                            acc[2][jj] + bj, acc[3][jj] + bj);
            *reinterpret_cast<float4*>(dst + vbase + 64 + tx * 4) =
                make_float4(acc[4][jj] + bj, acc[5][jj] + bj,
                            acc[6][jj] + bj, acc[7][jj] + bj);
        }
    }
}

// ---------------------------------------------------------------------------
// Kernel 4: deformable sampling with SMEM-staged neighborhood window.
// Block = 4x4x2 voxel tile x ONE group; 128 threads = 32 vox x 4 ch-lanes.
// Window = 8x8x6 positions x 32ch fp16 = 24KB smem, staged with coalesced
// 512B rows. All 8 trilinear corners come from LDS.128; rare out-of-window
// points fall back to clamped global loads (correctness for any offsets).
// ---------------------------------------------------------------------------
__global__ void __launch_bounds__(128) k_samp() {
    int bid = blockIdx.x;            // 2048 = 1024 tiles x 2 groups
    int gi = bid & 1;
    int tile = bid >> 1;
    int tbx = tile & 7, tby = (tile >> 3) & 7, tbz = tile >> 6;  // tbz in [0,15]
    int tid = threadIdx.x;

    __shared__ __align__(16) __half s_win[6 * 8 * 8 * GC];  // [lz][ly][lx][32ch] 24KB
    __shared__ float s_off[32][81];
    __shared__ float s_m[32][28];

    int W0x = tbx * 4, W0y = tby * 4, W0z = tbz * 2;  // window origin, padded coords

    // stage window: 384 positions x 4 uint4 = 1536 uint4, rows 512B-coalesced
    {
        const uint4* src = reinterpret_cast<const uint4*>(g_xph + (size_t)gi * HVOL);
        uint4* dst = reinterpret_cast<uint4*>(s_win);
#pragma unroll
        for (int i = 0; i < 12; i++) {
            int idx4 = i * 128 + tid;
            int pos = idx4 >> 2, q = idx4 & 3;
            int lz = pos >> 6, rem = pos & 63, ly = rem >> 3, lx = rem & 7;
            int gp = ((W0z + lz) * DP2 + W0y + ly) * DP2 + W0x + lx;
            dst[idx4] = src[gp * 4 + q];
        }
    }
    // stage offsets + mask logits
    for (int idx = tid; idx < 32 * 81; idx += 128) {
        int j = idx >> 5, vl = idx & 31;
        int vx = tbx * 4 + (vl & 3), vy = tby * 4 + ((vl >> 2) & 3), vz = tbz * 2 + (vl >> 4);
        s_off[vl][j] = g_off[(gi * 81 + j) * NVOX + (vz << 10) + (vy << 5) + vx];
    }
    for (int idx = tid; idx < 32 * 27; idx += 128) {
        int j = idx >> 5, vl = idx & 31;
        int vx = tbx * 4 + (vl & 3), vy = tby * 4 + ((vl >> 2) & 3), vz = tbz * 2 + (vl >> 4);
        s_m[vl][j] = g_mask[(gi * 27 + j) * NVOX + (vz << 10) + (vy << 5) + vx];
    }
    __syncthreads();

    // softmax over 27 points, one thread per voxel
    if (tid < 32) {
        float* m = s_m[tid];
        float mx = -1e30f;
#pragma unroll
        for (int p = 0; p < NP; p++) mx = fmaxf(mx, m[p]);
        float s = 0.f;
#pragma unroll
        for (int p = 0; p < NP; p++) { float e = __expf(m[p] - mx); m[p] = e; s += e; }
        float inv = 1.f / s;
#pragma unroll
        for (int p = 0; p < NP; p++) m[p] *= inv;
    }
    __syncthreads();

    int vv = tid >> 2;               // local voxel 0..31
    int c8 = tid & 3;                // 8 channels via float4 of halves
    int lxv = vv & 3, lyv = (vv >> 2) & 3, lzv = vv >> 4;

    const float4* win4 = reinterpret_cast<const float4*>(s_win);
    const float4* vol4 = reinterpret_cast<const float4*>(g_xph) + (size_t)gi * HVOL4 + c8;
    const float* offp = s_off[vv];
    const float* mp   = s_m[vv];

    float acc[8];
#pragma unroll
    for (int e = 0; e < 8; e++) acc[e] = 0.f;

    int kx = 0, ky = 0, kz = 0;
#pragma unroll 1
    for (int p = 0; p < NP; p++) {
        float ox = offp[p * 3 + 0];
        float oy = offp[p * 3 + 1];
        float oz = offp[p * 3 + 2];
        // window-local sample coords: lxv + kx + 1 + scaled off
        float sx = (float)(lxv + kx + 1) + 0.25f * ox;
        float sy = (float)(lyv + ky + 1) + 0.5f  * oy;
        float sz = (float)(lzv + kz + 1) + 0.5f  * oz;
        if (++kx == 3) { kx = 0; if (++ky == 3) { ky = 0; ++kz; } }

        float xf = floorf(sx), yf = floorf(sy), zf = floorf(sz);
        float fx = sx - xf, fy = sy - yf, fz = sz - zf;
        int x0 = (int)xf, y0 = (int)yf, z0 = (int)zf;

        float4 t000, t001, t010, t011, t100, t101, t110, t111;
        if ((unsigned)x0 < 7u && (unsigned)y0 < 7u && (unsigned)z0 < 5u) {
            // in-window fast path: LDS.128
            int p000 = ((z0 * 8 + y0) * 8 + x0) * 4 + c8;
            t000 = win4[p000];       t001 = win4[p000 + 4];
            t010 = win4[p000 + 32];  t011 = win4[p000 + 36];
            t100 = win4[p000 + 256]; t101 = win4[p000 + 260];
            t110 = win4[p000 + 288]; t111 = win4[p000 + 292];
        } else {
            // rare fallback: clamped global loads (zero ring handles OOB)
            int gx0 = x0 + W0x, gy0 = y0 + W0y, gz0 = z0 + W0z;
            int x0c = min(max(gx0, 0), DP2 - 1),     y0c = min(max(gy0, 0), DP2 - 1);
            int z0c = min(max(gz0, 0), DP2 - 1);
            int x1c = min(max(gx0 + 1, 0), DP2 - 1), y1c = min(max(gy0 + 1, 0), DP2 - 1);
            int z1c = min(max(gz0 + 1, 0), DP2 - 1);
            int zy00 = (z0c * DP2 + y0c) * DP2;
            int zy01 = (z0c * DP2 + y1c) * DP2;
            int zy10 = (z1c * DP2 + y0c) * DP2;
            int zy11 = (z1c * DP2 + y1c) * DP2;
            t000 = vol4[(zy00 + x0c) << 2]; t001 = vol4[(zy00 + x1c) << 2];
            t010 = vol4[(zy01 + x0c) << 2]; t011 = vol4[(zy01 + x1c) << 2];
            t100 = vol4[(zy10 + x0c) << 2]; t101 = vol4[(zy10 + x1c) << 2];
            t110 = vol4[(zy11 + x0c) << 2]; t111 = vol4[(zy11 + x1c) << 2];
        }

        float m = mp[p];
        float gx1 = fx, gx0 = 1.f - fx;
        float gy1 = fy, gy0 = 1.f - fy;
        float gz1 = fz, gz0 = 1.f - fz;
        float w00 = gz0 * gy0 * m, w01 = gz0 * gy1 * m;
        float w10 = gz1 * gy0 * m, w11 = gz1 * gy1 * m;
        float w000 = w00 * gx0, w001 = w00 * gx1;
        float w010 = w01 * gx0, w011 = w01 * gx1;
        float w100 = w10 * gx0, w101 = w10 * gx1;
        float w110 = w11 * gx0, w111 = w11 * gx1;

#define TAP(T, W) { \
        const __half2* hh = reinterpret_cast<const __half2*>(&T); \
        float2 f0 = __half22float2(hh[0]); \
        float2 f1 = __half22float2(hh[1]); \
        float2 f2 = __half22float2(hh[2]); \
        float2 f3 = __half22float2(hh[3]); \
        acc[0] = fmaf(W, f0.x, acc[0]); acc[1] = fmaf(W, f0.y, acc[1]); \
        acc[2] = fmaf(W, f1.x, acc[2]); acc[3] = fmaf(W, f1.y, acc[3]); \
        acc[4] = fmaf(W, f2.x, acc[4]); acc[5] = fmaf(W, f2.y, acc[5]); \
        acc[6] = fmaf(W, f3.x, acc[6]); acc[7] = fmaf(W, f3.y, acc[7]); }
        TAP(t000, w000) TAP(t001, w001) TAP(t010, w010) TAP(t011, w011)
        TAP(t100, w100) TAP(t101, w101) TAP(t110, w110) TAP(t111, w111)
#undef TAP
    }

    // write sampled result, c-major [c][v]
    int ix = tbx * 4 + lxv, iy = tby * 4 + lyv, iz = tbz * 2 + lzv;
    int v = (iz << 10) + (iy << 5) + ix;
    int cbase = gi * GC + c8 * 8;
#pragma unroll
    for (int e = 0; e < 8; e++)
        g_samp[(cbase + e) * NVOX + v] = acc[e];
}

// ---------------------------------------------------------------------------
// Kernel 5: output GEMM. out[v][oc] = g_samp[c][v]^T @ out_w[c][oc] + out_b.
// ---------------------------------------------------------------------------
__global__ void __launch_bounds__(256)
k_out(const float* __restrict__ out_w, const float* __restrict__ out_b,
      float* __restrict__ out) {
    int vbase = blockIdx.x * 128;
    int tid = threadIdx.x;
    __shared__ float sA[64 * 128];
    __shared__ float sB[64 * 64];

#pragma unroll
    for (int i = 0; i < 4; i++) {
        int lin = i * 1024 + tid * 4;
        *reinterpret_cast<float4*>(&sB[lin]) =
            *reinterpret_cast<const float4*>(&out_w[lin]);
    }
#pragma unroll
    for (int i = 0; i < 8; i++) {
        int lin = i * 1024 + tid * 4;
        int k = lin >> 7, vl = lin & 127;
        *reinterpret_cast<float4*>(&sA[lin]) =
            *reinterpret_cast<const float4*>(&g_samp[k * NVOX + vbase + vl]);
    }
    __syncthreads();

    int tx = tid & 15, ty = tid >> 4;
    float acc[8][4];
#pragma unroll
    for (int i = 0; i < 8; i++)
#pragma unroll
        for (int j = 0; j < 4; j++) acc[i][j] = 0.f;

    const float4* A4 = reinterpret_cast<const float4*>(sA);
    const float4* B4 = reinterpret_cast<const float4*>(sB);
#pragma unroll 8
    for (int k = 0; k < 64; k++) {
        float4 a0 = A4[k * 32 + tx];
        float4 a1 = A4[k * 32 + 16 + tx];
        float4 b  = B4[k * 16 + ty];
        float av[8] = {a0.x, a0.y, a0.z, a0.w, a1.x, a1.y, a1.z, a1.w};
        float bv[4] = {b.x, b.y, b.z, b.w};
#pragma unroll
        for (int i = 0; i < 8; i++)
#pragma unroll
            for (int j = 0; j < 4; j++)
                acc[i][j] = fmaf(av[i], bv[j], acc[i][j]);
    }

    float4 b4 = *reinterpret_cast<const float4*>(&out_b[ty * 4]);
#pragma unroll
    for (int vi = 0; vi < 8; vi++) {
        int v = vbase + ((vi & 4) << 4) + tx * 4 + (vi & 3);
        *reinterpret_cast<float4*>(&out[v * NC + ty * 4]) =
            make_float4(acc[vi][0] + b4.x, acc[vi][1] + b4.y,
                        acc[vi][2] + b4.z, acc[vi][3] + b4.w);
    }
}

// ---------------------------------------------------------------------------
extern "C" void kernel_launch(void* const* d_in, const int* in_sizes, int n_in,
                              void* d_out, int out_size) {
    const float* x      = (const float*)d_in[0];
    const float* dw_w   = (const float*)d_in[1];
    const float* gn_w   = (const float*)d_in[2];
    const float* gn_b   = (const float*)d_in[3];
    const float* inp_w  = (const float*)d_in[4];
    const float* inp_b  = (const float*)d_in[5];
    const float* off_w  = (const float*)d_in[6];
    const float* off_b  = (const float*)d_in[7];
    const float* mask_w = (const float*)d_in[8];
    const float* mask_b = (const float*)d_in[9];
    const float* out_w  = (const float*)d_in[10];
    const float* out_b  = (const float*)d_in[11];
    float* out = (float*)d_out;

    k_init<<<(NC * NJP + 255) / 256, 256>>>(inp_w, off_w, mask_w, inp_b, off_b, mask_b);
    k_dw<<<dim3(32, 64), 256>>>(x, dw_w);
    k_stats<<<1, 1024>>>();
    k_point<<<dim3(NVOX / 128, 5), 256>>>(x, gn_w, gn_b);
    k_samp<<<2048, 128>>>();
    k_out<<<NVOX / 128, 256>>>(out_w, out_b, out);
}

// round 12
// speedup vs baseline: 1.1638x; 1.0239x over previous
#include <cuda_runtime.h>
#include <cuda_fp16.h>
#include <math.h>

// Problem constants
#define NVOX 32768          // 32*32*32 voxels
#define NC   64             // channels
#define DP2  36             // padded dim + extra zero ring
#define GC   32             // channels per group
#define NG   2              // groups
#define NP   27             // kernel points
#define NOFF 162            // G*P*3
#define NMSK 54             // G*P
#define NJP  320            // padded j rows: 64 inp | 162 off | 54 mask | 40 zero
#define HVOL  (DP2*DP2*DP2*GC)  // halves per group = 1492992
#define HVOL4 (HVOL/8)          // float4 (8 halves) per group
#define KDW_BLOCKS 2048

// ---- scratch (static device globals; zero-initialized at module load) ----
__device__ __align__(256) float  g_xc[NC*NVOX];     // depthwise conv out, c-major [c][v]
__device__ __align__(256) __half g_xph[NG*HVOL];    // fp16 ring-padded projected volume
__device__ __align__(256) float  g_off[NOFF*NVOX];  // offsets, transposed [j][v]
__device__ __align__(256) float  g_mask[NMSK*NVOX]; // mask logits, transposed [j][v]
__device__ __align__(256) float  g_samp[NC*NVOX];   // sampled+masked result, c-major [c][v]
__device__ float g_part[KDW_BLOCKS*2];
__device__ float g_stats[2];
__device__ __align__(256) float g_wtT[NC*NJP];      // weights [k][j], j-reordered+padded
__device__ float g_bias[NJP];

// ---------------------------------------------------------------------------
// Kernel 0: build reordered weight matrix [k][j] + bias
// ---------------------------------------------------------------------------
__global__ void k_init(const float* __restrict__ inp_w, const float* __restrict__ off_w,
                       const float* __restrict__ mask_w,
                       const float* __restrict__ inp_b, const float* __restrict__ off_b,
                       const float* __restrict__ mask_b) {
    int gid = blockIdx.x * 256 + threadIdx.x;
    if (gid < NC * NJP) {
        int k = gid / NJP, j = gid - k * NJP;
        float v = 0.f;
        if (j < 64)       v = inp_w[k * NC + j];
        else if (j < 226) v = off_w[k * NOFF + (j - 64)];
        else if (j < 280) v = mask_w[k * NMSK + (j - 226)];
        g_wtT[gid] = v;
    }
    if (gid < NJP) {
        int j = gid;
        float b = 0.f;
        if (j < 64)       b = inp_b[j];
        else if (j < 226) b = off_b[j - 64];
        else if (j < 280) b = mask_b[j - 226];
        g_bias[j] = b;
    }
}

// ---------------------------------------------------------------------------
// Kernel 1: depthwise 3x3x3 conv via smem slab (3 z-slices + halo).
// ---------------------------------------------------------------------------
__global__ void k_dw(const float* __restrict__ x, const float* __restrict__ dw_w) {
    int bz = blockIdx.x, c = blockIdx.y;
    int tid = threadIdx.x;
    __shared__ float s[3][34][34];
    __shared__ float sh[8][2];

    const float* xs = x + c * NVOX;
    for (int i = tid; i < 3 * 34 * 34; i += 256) {
        int sl = i / 1156;
        int rem = i - sl * 1156;
        int yy = rem / 34;
        int xx = rem - yy * 34;
        int z = bz + sl - 1, y = yy - 1, xg = xx - 1;
        float val = 0.f;
        if ((unsigned)z < 32u && (unsigned)y < 32u && (unsigned)xg < 32u)
            val = xs[(z << 10) + (y << 5) + xg];
        s[sl][yy][xx] = val;
    }
    float w[27];
#pragma unroll
    for (int k = 0; k < 27; k++) w[k] = __ldg(dw_w + c * 27 + k);
    __syncthreads();

    float ls = 0.f, ls2 = 0.f;
#pragma unroll
    for (int q = 0; q < 4; q++) {
        int vloc = q * 256 + tid;
        int iy = vloc >> 5, ix = vloc & 31;
        float acc = 0.f;
#pragma unroll
        for (int kz = 0; kz < 3; kz++)
#pragma unroll
            for (int ky = 0; ky < 3; ky++)
#pragma unroll
                for (int kx = 0; kx < 3; kx++)
                    acc = fmaf(w[kz*9 + ky*3 + kx], s[kz][iy + ky][ix + kx], acc);
        g_xc[c * NVOX + (bz << 10) + vloc] = acc;
        ls += acc; ls2 += acc * acc;
    }

#pragma unroll
    for (int o = 16; o > 0; o >>= 1) {
        ls  += __shfl_down_sync(0xffffffffu, ls,  o);
        ls2 += __shfl_down_sync(0xffffffffu, ls2, o);
    }
    int lane = tid & 31, warp = tid >> 5;
    if (lane == 0) { sh[warp][0] = ls; sh[warp][1] = ls2; }
    __syncthreads();
    if (tid == 0) {
        float S = 0.f, S2 = 0.f;
#pragma unroll
        for (int i = 0; i < 8; i++) { S += sh[i][0]; S2 += sh[i][1]; }
        int bid = c * 32 + bz;
        g_part[bid * 2]     = S;
        g_part[bid * 2 + 1] = S2;
    }
}

// ---------------------------------------------------------------------------
// Kernel 2: finalize mean / rstd
// ---------------------------------------------------------------------------
__global__ void k_stats() {
    int tid = threadIdx.x;
    float s = 0.f, s2 = 0.f;
    for (int i = tid; i < KDW_BLOCKS; i += 1024) {
        float2 p = reinterpret_cast<const float2*>(g_part)[i];
        s += p.x; s2 += p.y;
    }
#pragma unroll
    for (int o = 16; o > 0; o >>= 1) {
        s  += __shfl_down_sync(0xffffffffu, s,  o);
        s2 += __shfl_down_sync(0xffffffffu, s2, o);
    }
    __shared__ float sh[32][2];
    int lane = tid & 31, wid = tid >> 5;
    if (lane == 0) { sh[wid][0] = s; sh[wid][1] = s2; }
    __syncthreads();
    if (tid == 0) {
        float S = 0.f, S2 = 0.f;
#pragma unroll
        for (int i = 0; i < 32; i++) { S += sh[i][0]; S2 += sh[i][1]; }
        float n   = (float)(NVOX * NC);
        float mu  = S / n;
        float var = S2 / n - mu * mu;
        g_stats[0] = mu;
        g_stats[1] = rsqrtf(var + 1e-5f);
    }
}

// ---------------------------------------------------------------------------
// Kernel 3: tiled GEMM. C[v][j] = A[v][k] * W[k][j]. grid (256, 5), 256 thr.
// ---------------------------------------------------------------------------
__global__ void __launch_bounds__(256)
k_point(const float* __restrict__ x,
        const float* __restrict__ gn_w, const float* __restrict__ gn_b) {
    int jt = blockIdx.y;
    int vbase = blockIdx.x * 128;
    int tid = threadIdx.x;
    __shared__ float sA[64 * 128];
    __shared__ float sB[64 * 64];

#pragma unroll
    for (int i = 0; i < 4; i++) {
        int lin = i * 1024 + tid * 4;
        int k = lin >> 6, j = lin & 63;
        *reinterpret_cast<float4*>(&sB[lin]) =
            *reinterpret_cast<const float4*>(&g_wtT[k * NJP + jt * 64 + j]);
    }
    if (jt == 0) {
#pragma unroll
        for (int i = 0; i < 8; i++) {
            int lin = i * 1024 + tid * 4;
            int k = lin >> 7, vl = lin & 127;
            *reinterpret_cast<float4*>(&sA[lin]) =
                *reinterpret_cast<const float4*>(&x[k * NVOX + vbase + vl]);
        }
    } else {
        float mu = g_stats[0], rstd = g_stats[1];
#pragma unroll
        for (int i = 0; i < 8; i++) {
            int lin = i * 1024 + tid * 4;
            int k = lin >> 7, vl = lin & 127;
            float gw = __ldg(gn_w + k) * rstd;
            float gb = __ldg(gn_b + k) - mu * gw;
            float4 xv = *reinterpret_cast<const float4*>(&g_xc[k * NVOX + vbase + vl]);
            float r[4] = {xv.x, xv.y, xv.z, xv.w};
#pragma unroll
            for (int e = 0; e < 4; e++) {
                float xn = r[e] * gw + gb;
                float u = xn + 0.044715f * xn * xn * xn;
                r[e] = xn / (1.f + __expf(-1.5957691216057308f * u));
            }
            *reinterpret_cast<float4*>(&sA[lin]) = make_float4(r[0], r[1], r[2], r[3]);
        }
    }
    __syncthreads();

    int tx = tid & 15, ty = tid >> 4;
    float acc[8][4];
#pragma unroll
    for (int i = 0; i < 8; i++)
#pragma unroll
        for (int j = 0; j < 4; j++) acc[i][j] = 0.f;

    const float4* A4 = reinterpret_cast<const float4*>(sA);
    const float4* B4 = reinterpret_cast<const float4*>(sB);
#pragma unroll 8
    for (int k = 0; k < 64; k++) {
        float4 a0 = A4[k * 32 + tx];
        float4 a1 = A4[k * 32 + 16 + tx];
        float4 b  = B4[k * 16 + ty];
        float av[8] = {a0.x, a0.y, a0.z, a0.w, a1.x, a1.y, a1.z, a1.w};
        float bv[4] = {b.x, b.y, b.z, b.w};
#pragma unroll
        for (int i = 0; i < 8; i++)
#pragma unroll
            for (int j = 0; j < 4; j++)
                acc[i][j] = fmaf(av[i], bv[j], acc[i][j]);
    }

    if (jt == 0) {
        int o = ty * 4;
        int g = o >> 5, ch = o & 31;
        float4 b4 = *reinterpret_cast<const float4*>(&g_bias[o]);
#pragma unroll
        for (int vi = 0; vi < 8; vi++) {
            int v = vbase + ((vi & 4) << 4) + tx * 4 + (vi & 3);
            int iz = v >> 10, iy = (v >> 5) & 31, ix = v & 31;
            int pos = (((g * DP2 + iz + 2) * DP2 + iy + 2) * DP2 + ix + 2);
            __half2 h01 = __floats2half2_rn(acc[vi][0] + b4.x, acc[vi][1] + b4.y);
            __half2 h23 = __floats2half2_rn(acc[vi][2] + b4.z, acc[vi][3] + b4.w);
            uint2 u;
            u.x = *reinterpret_cast<unsigned*>(&h01);
            u.y = *reinterpret_cast<unsigned*>(&h23);
            *reinterpret_cast<uint2*>(&g_xph[(pos << 5) + ch]) = u;
        }
    } else {
#pragma unroll
        for (int jj = 0; jj < 4; jj++) {
            int j = jt * 64 + ty * 4 + jj;
            float* dst;
            if (j < 226)      dst = g_off  + (j - 64)  * NVOX;
            else if (j < 280) dst = g_mask + (j - 226) * NVOX;
            else continue;
            float bj = g_bias[j];
            *reinterpret_cast<float4*>(dst + vbase + tx * 4) =
                make_float4(acc[0][jj] + bj, acc[1][jj] + bj,
                            acc[2][jj] + bj, acc[3][jj] + bj);
            *reinterpret_cast<float4*>(dst + vbase + 64 + tx * 4) =
                make_float4(acc[4][jj] + bj, acc[5][jj] + bj,
                            acc[6][jj] + bj, acc[7][jj] + bj);
        }
    }
}

// ---------------------------------------------------------------------------
// Kernel 4: deformable sampling, SMEM window + HFMA2 inner loop.
// Block = 4x4x4 voxel tile x ONE group; 256 threads = 64 vox x 4 ch-lanes.
// Window = 8x8x8 positions x 32ch fp16 = 32KB. Trilinear accumulation per
// point done in half2 (HFMA2); mask-weighted sum across points in fp32.
// ---------------------------------------------------------------------------
__global__ void __launch_bounds__(256) k_samp() {
    int bid = blockIdx.x;            // 1024 = 512 tiles x 2 groups
    int gi = bid & 1;
    int tile = bid >> 1;
    int tbx = tile & 7, tby = (tile >> 3) & 7, tbz = tile >> 6;  // each in [0,7]
    int tid = threadIdx.x;

    __shared__ __align__(16) __half s_win[8 * 8 * 8 * GC];  // 32KB
    __shared__ float s_off[64][81];
    __shared__ float s_m[64][28];

    int W0x = tbx * 4, W0y = tby * 4, W0z = tbz * 4;  // window origin (padded coords)

    // stage window: 512 positions x 4 uint4 = 2048 uint4
    {
        const uint4* src = reinterpret_cast<const uint4*>(g_xph + (size_t)gi * HVOL);
        uint4* dst = reinterpret_cast<uint4*>(s_win);
#pragma unroll
        for (int i = 0; i < 8; i++) {
            int idx4 = i * 256 + tid;
            int pos = idx4 >> 2, q = idx4 & 3;
            int lz = pos >> 6, rem = pos & 63, ly = rem >> 3, lx = rem & 7;
            int gp = ((W0z + lz) * DP2 + W0y + ly) * DP2 + W0x + lx;
            dst[idx4] = src[gp * 4 + q];
        }
    }
    // stage offsets + mask logits
    for (int idx = tid; idx < 64 * 81; idx += 256) {
        int j = idx >> 6, vl = idx & 63;
        int vx = tbx * 4 + (vl & 3), vy = tby * 4 + ((vl >> 2) & 3), vz = tbz * 4 + (vl >> 4);
        s_off[vl][j] = g_off[(gi * 81 + j) * NVOX + (vz << 10) + (vy << 5) + vx];
    }
    for (int idx = tid; idx < 64 * 27; idx += 256) {
        int j = idx >> 6, vl = idx & 63;
        int vx = tbx * 4 + (vl & 3), vy = tby * 4 + ((vl >> 2) & 3), vz = tbz * 4 + (vl >> 4);
        s_m[vl][j] = g_mask[(gi * 27 + j) * NVOX + (vz << 10) + (vy << 5) + vx];
    }
    __syncthreads();

    // softmax over 27 points, one thread per voxel
    if (tid < 64) {
        float* m = s_m[tid];
        float mx = -1e30f;
#pragma unroll
        for (int p = 0; p < NP; p++) mx = fmaxf(mx, m[p]);
        float s = 0.f;
#pragma unroll
        for (int p = 0; p < NP; p++) { float e = __expf(m[p] - mx); m[p] = e; s += e; }
        float inv = 1.f / s;
#pragma unroll
        for (int p = 0; p < NP; p++) m[p] *= inv;
    }
    __syncthreads();

    int vv = tid >> 2;               // local voxel 0..63
    int c8 = tid & 3;                // 8 channels via float4 of halves
    int lxv = vv & 3, lyv = (vv >> 2) & 3, lzv = vv >> 4;

    const float4* win4 = reinterpret_cast<const float4*>(s_win);
    const float4* vol4 = reinterpret_cast<const float4*>(g_xph) + (size_t)gi * HVOL4 + c8;
    const float* offp = s_off[vv];
    const float* mp   = s_m[vv];

    float acc[8];
#pragma unroll
    for (int e = 0; e < 8; e++) acc[e] = 0.f;

    int kx = 0, ky = 0, kz = 0;
#pragma unroll 1
    for (int p = 0; p < NP; p++) {
        float ox = offp[p * 3 + 0];
        float oy = offp[p * 3 + 1];
        float oz = offp[p * 3 + 2];
        float sx = (float)(lxv + kx + 1) + 0.25f * ox;
        float sy = (float)(lyv + ky + 1) + 0.5f  * oy;
        float sz = (float)(lzv + kz + 1) + 0.5f  * oz;
        if (++kx == 3) { kx = 0; if (++ky == 3) { ky = 0; ++kz; } }

        float xf = floorf(sx), yf = floorf(sy), zf = floorf(sz);
        float fx = sx - xf, fy = sy - yf, fz = sz - zf;
        int x0 = (int)xf, y0 = (int)yf, z0 = (int)zf;

        float4 t000, t001, t010, t011, t100, t101, t110, t111;
        if ((unsigned)x0 < 7u && (unsigned)y0 < 7u && (unsigned)z0 < 7u) {
            int p000 = ((z0 * 8 + y0) * 8 + x0) * 4 + c8;
            t000 = win4[p000];       t001 = win4[p000 + 4];
            t010 = win4[p000 + 32];  t011 = win4[p000 + 36];
            t100 = win4[p000 + 256]; t101 = win4[p000 + 260];
            t110 = win4[p000 + 288]; t111 = win4[p000 + 292];
        } else {
            int gx0 = x0 + W0x, gy0 = y0 + W0y, gz0 = z0 + W0z;
            int x0c = min(max(gx0, 0), DP2 - 1),     y0c = min(max(gy0, 0), DP2 - 1);
            int z0c = min(max(gz0, 0), DP2 - 1);
            int x1c = min(max(gx0 + 1, 0), DP2 - 1), y1c = min(max(gy0 + 1, 0), DP2 - 1);
            int z1c = min(max(gz0 + 1, 0), DP2 - 1);
            int zy00 = (z0c * DP2 + y0c) * DP2;
            int zy01 = (z0c * DP2 + y1c) * DP2;
            int zy10 = (z1c * DP2 + y0c) * DP2;
            int zy11 = (z1c * DP2 + y1c) * DP2;
            t000 = vol4[(zy00 + x0c) << 2]; t001 = vol4[(zy00 + x1c) << 2];
            t010 = vol4[(zy01 + x0c) << 2]; t011 = vol4[(zy01 + x1c) << 2];
            t100 = vol4[(zy10 + x0c) << 2]; t101 = vol4[(zy10 + x1c) << 2];
            t110 = vol4[(zy11 + x0c) << 2]; t111 = vol4[(zy11 + x1c) << 2];
        }

        float gx1 = fx, gx0 = 1.f - fx;
        float gy1 = fy, gy0 = 1.f - fy;
        float gz1 = fz, gz0 = 1.f - fz;
        float w00 = gz0 * gy0, w01 = gz0 * gy1, w10 = gz1 * gy0, w11 = gz1 * gy1;

        // trilinear accumulation in half2 (4 HFMA2 per tap)
        __half2 h0 = __float2half2_rn(0.f), h1 = h0, h2 = h0, h3 = h0;
#define TAPH(T, W) { \
        __half2 wh = __float2half2_rn(W); \
        const __half2* hh = reinterpret_cast<const __half2*>(&T); \
        h0 = __hfma2(wh, hh[0], h0); h1 = __hfma2(wh, hh[1], h1); \
        h2 = __hfma2(wh, hh[2], h2); h3 = __hfma2(wh, hh[3], h3); }
        TAPH(t000, w00 * gx0) TAPH(t001, w00 * gx1)
        TAPH(t010, w01 * gx0) TAPH(t011, w01 * gx1)
        TAPH(t100, w10 * gx0) TAPH(t101, w10 * gx1)
        TAPH(t110, w11 * gx0) TAPH(t111, w11 * gx1)
#undef TAPH

        // mask-weighted accumulate in fp32
        float m = mp[p];
        float2 f0 = __half22float2(h0);
        float2 f1 = __half22float2(h1);
        float2 f2 = __half22float2(h2);
        float2 f3 = __half22float2(h3);
        acc[0] = fmaf(m, f0.x, acc[0]); acc[1] = fmaf(m, f0.y, acc[1]);
        acc[2] = fmaf(m, f1.x, acc[2]); acc[3] = fmaf(m, f1.y, acc[3]);
        acc[4] = fmaf(m, f2.x, acc[4]); acc[5] = fmaf(m, f2.y, acc[5]);
        acc[6] = fmaf(m, f3.x, acc[6]); acc[7] = fmaf(m, f3.y, acc[7]);
    }

    // write sampled result, c-major [c][v]
    int ix = tbx * 4 + lxv, iy = tby * 4 + lyv, iz = tbz * 4 + lzv;
    int v = (iz << 10) + (iy << 5) + ix;
    int cbase = gi * GC + c8 * 8;
#pragma unroll
    for (int e = 0; e < 8; e++)
        g_samp[(cbase + e) * NVOX + v] = acc[e];
}

// ---------------------------------------------------------------------------
// Kernel 5: output GEMM. out[v][oc] = g_samp[c][v]^T @ out_w[c][oc] + out_b.
// ---------------------------------------------------------------------------
__global__ void __launch_bounds__(256)
k_out(const float* __restrict__ out_w, const float* __restrict__ out_b,
      float* __restrict__ out) {
    int vbase = blockIdx.x * 128;
    int tid = threadIdx.x;
    __shared__ float sA[64 * 128];
    __shared__ float sB[64 * 64];

#pragma unroll
    for (int i = 0; i < 4; i++) {
        int lin = i * 1024 + tid * 4;
        *reinterpret_cast<float4*>(&sB[lin]) =
            *reinterpret_cast<const float4*>(&out_w[lin]);
    }
#pragma unroll
    for (int i = 0; i < 8; i++) {
        int lin = i * 1024 + tid * 4;
        int k = lin >> 7, vl = lin & 127;
        *reinterpret_cast<float4*>(&sA[lin]) =
            *reinterpret_cast<const float4*>(&g_samp[k * NVOX + vbase + vl]);
    }
    __syncthreads();

    int tx = tid & 15, ty = tid >> 4;
    float acc[8][4];
#pragma unroll
    for (int i = 0; i < 8; i++)
#pragma unroll
        for (int j = 0; j < 4; j++) acc[i][j] = 0.f;

    const float4* A4 = reinterpret_cast<const float4*>(sA);
    const float4* B4 = reinterpret_cast<const float4*>(sB);
#pragma unroll 8
    for (int k = 0; k < 64; k++) {
        float4 a0 = A4[k * 32 + tx];
        float4 a1 = A4[k * 32 + 16 + tx];
        float4 b  = B4[k * 16 + ty];
        float av[8] = {a0.x, a0.y, a0.z, a0.w, a1.x, a1.y, a1.z, a1.w};
        float bv[4] = {b.x, b.y, b.z, b.w};
#pragma unroll
        for (int i = 0; i < 8; i++)
#pragma unroll
            for (int j = 0; j < 4; j++)
                acc[i][j] = fmaf(av[i], bv[j], acc[i][j]);
    }

    float4 b4 = *reinterpret_cast<const float4*>(&out_b[ty * 4]);
#pragma unroll
    for (int vi = 0; vi < 8; vi++) {
        int v = vbase + ((vi & 4) << 4) + tx * 4 + (vi & 3);
        *reinterpret_cast<float4*>(&out[v * NC + ty * 4]) =
            make_float4(acc[vi][0] + b4.x, acc[vi][1] + b4.y,
                        acc[vi][2] + b4.z, acc[vi][3] + b4.w);
    }
}

// ---------------------------------------------------------------------------
extern "C" void kernel_launch(void* const* d_in, const int* in_sizes, int n_in,
                              void* d_out, int out_size) {
    const float* x      = (const float*)d_in[0];
    const float* dw_w   = (const float*)d_in[1];
    const float* gn_w   = (const float*)d_in[2];
    const float* gn_b   = (const float*)d_in[3];
    const float* inp_w  = (const float*)d_in[4];
    const float* inp_b  = (const float*)d_in[5];
    const float* off_w  = (const float*)d_in[6];
    const float* off_b  = (const float*)d_in[7];
    const float* mask_w = (const float*)d_in[8];
    const float* mask_b = (const float*)d_in[9];
    const float* out_w  = (const float*)d_in[10];
    const float* out_b  = (const float*)d_in[11];
    float* out = (float*)d_out;

    k_init<<<(NC * NJP + 255) / 256, 256>>>(inp_w, off_w, mask_w, inp_b, off_b, mask_b);
    k_dw<<<dim3(32, 64), 256>>>(x, dw_w);
    k_stats<<<1, 1024>>>();
    k_point<<<dim3(NVOX / 128, 5), 256>>>(x, gn_w, gn_b);
    k_samp<<<1024, 256>>>();
    k_out<<<NVOX / 128, 256>>>(out_w, out_b, out);
}

// round 14
// speedup vs baseline: 1.2650x; 1.0869x over previous
#include <cuda_runtime.h>
#include <cuda_fp16.h>
#include <math.h>

// Problem constants
#define NVOX 32768          // 32*32*32 voxels
#define NC   64             // channels
#define DP2  36             // padded dim + extra zero ring
#define GC   32             // channels per group
#define NG   2              // groups
#define NP   27             // kernel points
#define NOFF 162            // G*P*3
#define NMSK 54             // G*P
#define NJP  320            // padded j rows: 64 inp | 162 off | 54 mask | 40 zero
#define HVOL  (DP2*DP2*DP2*GC)  // halves per group = 1492992
#define HVOL4 (HVOL/8)          // float4 (8 halves) per group
#define KDW_BLOCKS 2048
#define SAPAD 72            // sA/sB row stride in halves (conflict-free fragments)
#define SCPAD 68            // sC row stride in floats

// ---- scratch (static device globals; zero-initialized at module load) ----
__device__ __align__(256) float  g_xc[NC*NVOX];     // depthwise conv out, c-major [c][v]
__device__ __align__(256) __half g_xph[NG*HVOL];    // fp16 ring-padded projected volume
__device__ __align__(256) float  g_off[NOFF*NVOX];  // offsets, transposed [j][v]
__device__ __align__(256) float  g_mask[NMSK*NVOX]; // mask logits, transposed [j][v]
__device__ __align__(256) float  g_samp[NC*NVOX];   // sampled+masked result, c-major [c][v]
__device__ float g_part[KDW_BLOCKS*2];
__device__ float g_stats[2];
__device__ __align__(256) float g_wtT[NC*NJP];      // weights [k][j], j-reordered+padded
__device__ float g_bias[NJP];

// ---------------------------------------------------------------------------
// Kernel 0: build reordered weight matrix [k][j] + bias
// ---------------------------------------------------------------------------
__global__ void k_init(const float* __restrict__ inp_w, const float* __restrict__ off_w,
                       const float* __restrict__ mask_w,
                       const float* __restrict__ inp_b, const float* __restrict__ off_b,
                       const float* __restrict__ mask_b) {
    int gid = blockIdx.x * 256 + threadIdx.x;
    if (gid < NC * NJP) {
        int k = gid / NJP, j = gid - k * NJP;
        float v = 0.f;
        if (j < 64)       v = inp_w[k * NC + j];
        else if (j < 226) v = off_w[k * NOFF + (j - 64)];
        else if (j < 280) v = mask_w[k * NMSK + (j - 226)];
        g_wtT[gid] = v;
    }
    if (gid < NJP) {
        int j = gid;
        float b = 0.f;
        if (j < 64)       b = inp_b[j];
        else if (j < 226) b = off_b[j - 64];
        else if (j < 280) b = mask_b[j - 226];
        g_bias[j] = b;
    }
}

// ---------------------------------------------------------------------------
// Kernel 1: depthwise 3x3x3 conv via smem slab (3 z-slices + halo).
// ---------------------------------------------------------------------------
__global__ void k_dw(const float* __restrict__ x, const float* __restrict__ dw_w) {
    int bz = blockIdx.x, c = blockIdx.y;
    int tid = threadIdx.x;
    __shared__ float s[3][34][34];
    __shared__ float sh[8][2];

    const float* xs = x + c * NVOX;
    for (int i = tid; i < 3 * 34 * 34; i += 256) {
        int sl = i / 1156;
        int rem = i - sl * 1156;
        int yy = rem / 34;
        int xx = rem - yy * 34;
        int z = bz + sl - 1, y = yy - 1, xg = xx - 1;
        float val = 0.f;
        if ((unsigned)z < 32u && (unsigned)y < 32u && (unsigned)xg < 32u)
            val = xs[(z << 10) + (y << 5) + xg];
        s[sl][yy][xx] = val;
    }
    float w[27];
#pragma unroll
    for (int k = 0; k < 27; k++) w[k] = __ldg(dw_w + c * 27 + k);
    __syncthreads();

    float ls = 0.f, ls2 = 0.f;
#pragma unroll
    for (int q = 0; q < 4; q++) {
        int vloc = q * 256 + tid;
        int iy = vloc >> 5, ix = vloc & 31;
        float acc = 0.f;
#pragma unroll
        for (int kz = 0; kz < 3; kz++)
#pragma unroll
            for (int ky = 0; ky < 3; ky++)
#pragma unroll
                for (int kx = 0; kx < 3; kx++)
                    acc = fmaf(w[kz*9 + ky*3 + kx], s[kz][iy + ky][ix + kx], acc);
        g_xc[c * NVOX + (bz << 10) + vloc] = acc;
        ls += acc; ls2 += acc * acc;
    }

#pragma unroll
    for (int o = 16; o > 0; o >>= 1) {
        ls  += __shfl_down_sync(0xffffffffu, ls,  o);
        ls2 += __shfl_down_sync(0xffffffffu, ls2, o);
    }
    int lane = tid & 31, warp = tid >> 5;
    if (lane == 0) { sh[warp][0] = ls; sh[warp][1] = ls2; }
    __syncthreads();
    if (tid == 0) {
        float S = 0.f, S2 = 0.f;
#pragma unroll
        for (int i = 0; i < 8; i++) { S += sh[i][0]; S2 += sh[i][1]; }
        int bid = c * 32 + bz;
        g_part[bid * 2]     = S;
        g_part[bid * 2 + 1] = S2;
    }
}

// ---------------------------------------------------------------------------
// Kernel 2: finalize mean / rstd
// ---------------------------------------------------------------------------
__global__ void k_stats() {
    int tid = threadIdx.x;
    float s = 0.f, s2 = 0.f;
    for (int i = tid; i < KDW_BLOCKS; i += 1024) {
        float2 p = reinterpret_cast<const float2*>(g_part)[i];
        s += p.x; s2 += p.y;
    }
#pragma unroll
    for (int o = 16; o > 0; o >>= 1) {
        s  += __shfl_down_sync(0xffffffffu, s,  o);
        s2 += __shfl_down_sync(0xffffffffu, s2, o);
    }
    __shared__ float sh[32][2];
    int lane = tid & 31, wid = tid >> 5;
    if (lane == 0) { sh[wid][0] = s; sh[wid][1] = s2; }
    __syncthreads();
    if (tid == 0) {
        float S = 0.f, S2 = 0.f;
#pragma unroll
        for (int i = 0; i < 32; i++) { S += sh[i][0]; S2 += sh[i][1]; }
        float n   = (float)(NVOX * NC);
        float mu  = S / n;
        float var = S2 / n - mu * mu;
        g_stats[0] = mu;
        g_stats[1] = rsqrtf(var + 1e-5f);
    }
}

// ---------------------------------------------------------------------------
// mma helper: D += A*B, m16n8k16 fp16 -> fp32
// ---------------------------------------------------------------------------
__device__ __forceinline__ void mma16816(float* c, const unsigned* a, const unsigned* b) {
    asm volatile(
        "mma.sync.aligned.m16n8k16.row.col.f32.f16.f16.f32 "
        "{%0,%1,%2,%3}, {%4,%5,%6,%7}, {%8,%9}, {%0,%1,%2,%3};"
        : "+f"(c[0]), "+f"(c[1]), "+f"(c[2]), "+f"(c[3])
        : "r"(a[0]), "r"(a[1]), "r"(a[2]), "r"(a[3]), "r"(b[0]), "r"(b[1]));
}

__device__ __forceinline__ unsigned h2u(__half2 h) {
    return *reinterpret_cast<unsigned*>(&h);
}

// ---------------------------------------------------------------------------
// Kernel 3: tensor-core GEMM. C[v][j] = A[v][k] * W[k][j], fp16 x fp16 -> fp32.
// grid (256, 5), 256 threads. 8 warps, each m32 x n32 of the 128x64 tile.
// sA [128][72] half, sB [64][72] half (operands), sC [128][68] float (reuses
// the same smem region after mma completes). Epilogue identical to scalar.
// ---------------------------------------------------------------------------
__global__ void __launch_bounds__(256)
k_point(const float* __restrict__ x,
        const float* __restrict__ gn_w, const float* __restrict__ gn_b) {
    int jt = blockIdx.y;
    int vbase = blockIdx.x * 128;
    int tid = threadIdx.x;

    __shared__ __align__(16) char buf[128 * SCPAD * 4];   // 34816 B
    __half* sA = reinterpret_cast<__half*>(buf);                    // [128][72]
    __half* sB = reinterpret_cast<__half*>(buf + 128 * SAPAD * 2);  // [64][72]
    float*  sC = reinterpret_cast<float*>(buf);                     // [128][68]

    float mu = g_stats[0], rstd = g_stats[1];

    // ---- stage A: [128 v][64 k] fp16. thread: v-quad (tid&31), k-octet (tid>>5)
    {
        int v4 = tid & 31;
        int kb = tid >> 5;      // k-octet: k = kb*8 .. +7
#pragma unroll
        for (int half = 0; half < 2; half++) {
            float4 r[4];
#pragma unroll
            for (int kk = 0; kk < 4; kk++) {
                int k = kb * 8 + half * 4 + kk;
                if (jt == 0) {
                    r[kk] = *reinterpret_cast<const float4*>(&x[k * NVOX + vbase + v4 * 4]);
                } else {
                    float gw = __ldg(gn_w + k) * rstd;
                    float gb = __ldg(gn_b + k) - mu * gw;
                    float4 xv = *reinterpret_cast<const float4*>(&g_xc[k * NVOX + vbase + v4 * 4]);
                    float q[4] = {xv.x, xv.y, xv.z, xv.w};
#pragma unroll
                    for (int e = 0; e < 4; e++) {
                        float xn = q[e] * gw + gb;
                        float u = xn + 0.044715f * xn * xn * xn;
                        q[e] = xn / (1.f + __expf(-1.5957691216057308f * u));
                    }
                    r[kk] = make_float4(q[0], q[1], q[2], q[3]);
                }
            }
#pragma unroll
            for (int e = 0; e < 4; e++) {
                const float* f0 = reinterpret_cast<const float*>(&r[0]);
                const float* f1 = reinterpret_cast<const float*>(&r[1]);
                const float* f2 = reinterpret_cast<const float*>(&r[2]);
                const float* f3 = reinterpret_cast<const float*>(&r[3]);
                uint2 u;
                u.x = h2u(__floats2half2_rn(f0[e], f1[e]));
                u.y = h2u(__floats2half2_rn(f2[e], f3[e]));
                *reinterpret_cast<uint2*>(&sA[(v4 * 4 + e) * SAPAD + kb * 8 + half * 4]) = u;
            }
        }
    }
    // ---- stage B: [64 j][64 k] fp16 transpose of g_wtT. threads 0..127
    if (tid < 128) {
        int j4 = tid & 15;
        int kb = tid >> 4;      // 0..7
#pragma unroll
        for (int half = 0; half < 2; half++) {
            float4 r[4];
#pragma unroll
            for (int kk = 0; kk < 4; kk++) {
                int k = kb * 8 + half * 4 + kk;
                r[kk] = *reinterpret_cast<const float4*>(&g_wtT[k * NJP + jt * 64 + j4 * 4]);
            }
#pragma unroll
            for (int e = 0; e < 4; e++) {
                const float* f0 = reinterpret_cast<const float*>(&r[0]);
                const float* f1 = reinterpret_cast<const float*>(&r[1]);
                const float* f2 = reinterpret_cast<const float*>(&r[2]);
                const float* f3 = reinterpret_cast<const float*>(&r[3]);
                uint2 u;
                u.x = h2u(__floats2half2_rn(f0[e], f1[e]));
                u.y = h2u(__floats2half2_rn(f2[e], f3[e]));
                *reinterpret_cast<uint2*>(&sB[(j4 * 4 + e) * SAPAD + kb * 8 + half * 4]) = u;
            }
        }
    }
    __syncthreads();

    // ---- mma: warp w computes m32 (rows (w>>1)*32) x n32 (cols (w&1)*32)
    int w = tid >> 5, lane = tid & 31;
    int g = lane >> 2, t4 = lane & 3;
    int m0 = (w >> 1) * 32, n0 = (w & 1) * 32;
    float c[2][4][4];
#pragma unroll
    for (int mi = 0; mi < 2; mi++)
#pragma unroll
        for (int ni = 0; ni < 4; ni++)
#pragma unroll
            for (int e = 0; e < 4; e++) c[mi][ni][e] = 0.f;

#pragma unroll
    for (int kk = 0; kk < 4; kk++) {
        int k0 = kk * 16;
        unsigned a[2][4], b[4][2];
#pragma unroll
        for (int mi = 0; mi < 2; mi++) {
            int r = m0 + mi * 16;
            a[mi][0] = *reinterpret_cast<unsigned*>(&sA[(r + g) * SAPAD + k0 + 2 * t4]);
            a[mi][1] = *reinterpret_cast<unsigned*>(&sA[(r + 8 + g) * SAPAD + k0 + 2 * t4]);
            a[mi][2] = *reinterpret_cast<unsigned*>(&sA[(r + g) * SAPAD + k0 + 8 + 2 * t4]);
            a[mi][3] = *reinterpret_cast<unsigned*>(&sA[(r + 8 + g) * SAPAD + k0 + 8 + 2 * t4]);
        }
#pragma unroll
        for (int ni = 0; ni < 4; ni++) {
            int jr = n0 + ni * 8 + g;
            b[ni][0] = *reinterpret_cast<unsigned*>(&sB[jr * SAPAD + k0 + 2 * t4]);
            b[ni][1] = *reinterpret_cast<unsigned*>(&sB[jr * SAPAD + k0 + 8 + 2 * t4]);
        }
#pragma unroll
        for (int mi = 0; mi < 2; mi++)
#pragma unroll
            for (int ni = 0; ni < 4; ni++)
                mma16816(c[mi][ni], a[mi], b[ni]);
    }
    __syncthreads();   // all operand reads done; reuse smem as sC

    // ---- write C fragments to sC [128][68]
#pragma unroll
    for (int mi = 0; mi < 2; mi++)
#pragma unroll
        for (int ni = 0; ni < 4; ni++) {
            int r = m0 + mi * 16 + g;
            int cc = n0 + ni * 8 + 2 * t4;
            *reinterpret_cast<float2*>(&sC[r * SCPAD + cc]) =
                make_float2(c[mi][ni][0], c[mi][ni][1]);
            *reinterpret_cast<float2*>(&sC[(r + 8) * SCPAD + cc]) =
                make_float2(c[mi][ni][2], c[mi][ni][3]);
        }
    __syncthreads();

    // ---- epilogue (same structure as scalar version, reading sC)
    int tx = tid & 15, ty = tid >> 4;
    float acc[8][4];
#pragma unroll
    for (int vi = 0; vi < 8; vi++) {
        int vloc = ((vi & 4) << 4) + tx * 4 + (vi & 3);
        float4 q = *reinterpret_cast<float4*>(&sC[vloc * SCPAD + ty * 4]);
        acc[vi][0] = q.x; acc[vi][1] = q.y; acc[vi][2] = q.z; acc[vi][3] = q.w;
    }

    if (jt == 0) {
        int o = ty * 4;
        int gg = o >> 5, ch = o & 31;
        float4 b4 = *reinterpret_cast<const float4*>(&g_bias[o]);
#pragma unroll
        for (int vi = 0; vi < 8; vi++) {
            int v = vbase + ((vi & 4) << 4) + tx * 4 + (vi & 3);
            int iz = v >> 10, iy = (v >> 5) & 31, ix = v & 31;
            int pos = (((gg * DP2 + iz + 2) * DP2 + iy + 2) * DP2 + ix + 2);
            __half2 h01 = __floats2half2_rn(acc[vi][0] + b4.x, acc[vi][1] + b4.y);
            __half2 h23 = __floats2half2_rn(acc[vi][2] + b4.z, acc[vi][3] + b4.w);
            uint2 u;
            u.x = h2u(h01);
            u.y = h2u(h23);
            *reinterpret_cast<uint2*>(&g_xph[(pos << 5) + ch]) = u;
        }
    } else {
#pragma unroll
        for (int jj = 0; jj < 4; jj++) {
            int j = jt * 64 + ty * 4 + jj;
            float* dst;
            if (j < 226)      dst = g_off  + (j - 64)  * NVOX;
            else if (j < 280) dst = g_mask + (j - 226) * NVOX;
            else continue;
            float bj = g_bias[j];
            *reinterpret_cast<float4*>(dst + vbase + tx * 4) =
                make_float4(acc[0][jj] + bj, acc[1][jj] + bj,
                            acc[2][jj] + bj, acc[3][jj] + bj);
            *reinterpret_cast<float4*>(dst + vbase + 64 + tx * 4) =
                make_float4(acc[4][jj] + bj, acc[5][jj] + bj,
                            acc[6][jj] + bj, acc[7][jj] + bj);
        }
    }
}

// ---------------------------------------------------------------------------
// Kernel 4: deformable sampling, SMEM window + HFMA2 inner loop. (R12 form)
// ---------------------------------------------------------------------------
__global__ void __launch_bounds__(256) k_samp() {
    int bid = blockIdx.x;            // 1024 = 512 tiles x 2 groups
    int gi = bid & 1;
    int tile = bid >> 1;
    int tbx = tile & 7, tby = (tile >> 3) & 7, tbz = tile >> 6;
    int tid = threadIdx.x;

    __shared__ __align__(16) __half s_win[8 * 8 * 8 * GC];  // 32KB
    __shared__ float s_off[64][81];
    __shared__ float s_m[64][28];

    int W0x = tbx * 4, W0y = tby * 4, W0z = tbz * 4;

    {
        const uint4* src = reinterpret_cast<const uint4*>(g_xph + (size_t)gi * HVOL);
        uint4* dst = reinterpret_cast<uint4*>(s_win);
#pragma unroll
        for (int i = 0; i < 8; i++) {
            int idx4 = i * 256 + tid;
            int pos = idx4 >> 2, q = idx4 & 3;
            int lz = pos >> 6, rem = pos & 63, ly = rem >> 3, lx = rem & 7;
            int gp = ((W0z + lz) * DP2 + W0y + ly) * DP2 + W0x + lx;
            dst[idx4] = src[gp * 4 + q];
        }
    }
    for (int idx = tid; idx < 64 * 81; idx += 256) {
        int j = idx >> 6, vl = idx & 63;
        int vx = tbx * 4 + (vl & 3), vy = tby * 4 + ((vl >> 2) & 3), vz = tbz * 4 + (vl >> 4);
        s_off[vl][j] = g_off[(gi * 81 + j) * NVOX + (vz << 10) + (vy << 5) + vx];
    }
    for (int idx = tid; idx < 64 * 27; idx += 256) {
        int j = idx >> 6, vl = idx & 63;
        int vx = tbx * 4 + (vl & 3), vy = tby * 4 + ((vl >> 2) & 3), vz = tbz * 4 + (vl >> 4);
        s_m[vl][j] = g_mask[(gi * 27 + j) * NVOX + (vz << 10) + (vy << 5) + vx];
    }
    __syncthreads();

    if (tid < 64) {
        float* m = s_m[tid];
        float mx = -1e30f;
#pragma unroll
        for (int p = 0; p < NP; p++) mx = fmaxf(mx, m[p]);
        float s = 0.f;
#pragma unroll
        for (int p = 0; p < NP; p++) { float e = __expf(m[p] - mx); m[p] = e; s += e; }
        float inv = 1.f / s;
#pragma unroll
        for (int p = 0; p < NP; p++) m[p] *= inv;
    }
    __syncthreads();

    int vv = tid >> 2;
    int c8 = tid & 3;
    int lxv = vv & 3, lyv = (vv >> 2) & 3, lzv = vv >> 4;

    const float4* win4 = reinterpret_cast<const float4*>(s_win);
    const float4* vol4 = reinterpret_cast<const float4*>(g_xph) + (size_t)gi * HVOL4 + c8;
    const float* offp = s_off[vv];
    const float* mp   = s_m[vv];

    float acc[8];
#pragma unroll
    for (int e = 0; e < 8; e++) acc[e] = 0.f;

    int kx = 0, ky = 0, kz = 0;
#pragma unroll 1
    for (int p = 0; p < NP; p++) {
        float ox = offp[p * 3 + 0];
        float oy = offp[p * 3 + 1];
        float oz = offp[p * 3 + 2];
        float sx = (float)(lxv + kx + 1) + 0.25f * ox;
        float sy = (float)(lyv + ky + 1) + 0.5f  * oy;
        float sz = (float)(lzv + kz + 1) + 0.5f  * oz;
        if (++kx == 3) { kx = 0; if (++ky == 3) { ky = 0; ++kz; } }

        float xf = floorf(sx), yf = floorf(sy), zf = floorf(sz);
        float fx = sx - xf, fy = sy - yf, fz = sz - zf;
        int x0 = (int)xf, y0 = (int)yf, z0 = (int)zf;

        float4 t000, t001, t010, t011, t100, t101, t110, t111;
        if ((unsigned)x0 < 7u && (unsigned)y0 < 7u && (unsigned)z0 < 7u) {
            int p000 = ((z0 * 8 + y0) * 8 + x0) * 4 + c8;
            t000 = win4[p000];       t001 = win4[p000 + 4];
            t010 = win4[p000 + 32];  t011 = win4[p000 + 36];
            t100 = win4[p000 + 256]; t101 = win4[p000 + 260];
            t110 = win4[p000 + 288]; t111 = win4[p000 + 292];
        } else {
            int gx0 = x0 + W0x, gy0 = y0 + W0y, gz0 = z0 + W0z;
            int x0c = min(max(gx0, 0), DP2 - 1),     y0c = min(max(gy0, 0), DP2 - 1);
            int z0c = min(max(gz0, 0), DP2 - 1);
            int x1c = min(max(gx0 + 1, 0), DP2 - 1), y1c = min(max(gy0 + 1, 0), DP2 - 1);
            int z1c = min(max(gz0 + 1, 0), DP2 - 1);
            int zy00 = (z0c * DP2 + y0c) * DP2;
            int zy01 = (z0c * DP2 + y1c) * DP2;
            int zy10 = (z1c * DP2 + y0c) * DP2;
            int zy11 = (z1c * DP2 + y1c) * DP2;
            t000 = vol4[(zy00 + x0c) << 2]; t001 = vol4[(zy00 + x1c) << 2];
            t010 = vol4[(zy01 + x0c) << 2]; t011 = vol4[(zy01 + x1c) << 2];
            t100 = vol4[(zy10 + x0c) << 2]; t101 = vol4[(zy10 + x1c) << 2];
            t110 = vol4[(zy11 + x0c) << 2]; t111 = vol4[(zy11 + x1c) << 2];
        }

        float gx1 = fx, gx0 = 1.f - fx;
        float gy1 = fy, gy0 = 1.f - fy;
        float gz1 = fz, gz0 = 1.f - fz;
        float w00 = gz0 * gy0, w01 = gz0 * gy1, w10 = gz1 * gy0, w11 = gz1 * gy1;

        __half2 h0 = __float2half2_rn(0.f), h1 = h0, h2 = h0, h3 = h0;
#define TAPH(T, W) { \
        __half2 wh = __float2half2_rn(W); \
        const __half2* hh = reinterpret_cast<const __half2*>(&T); \
        h0 = __hfma2(wh, hh[0], h0); h1 = __hfma2(wh, hh[1], h1); \
        h2 = __hfma2(wh, hh[2], h2); h3 = __hfma2(wh, hh[3], h3); }
        TAPH(t000, w00 * gx0) TAPH(t001, w00 * gx1)
        TAPH(t010, w01 * gx0) TAPH(t011, w01 * gx1)
        TAPH(t100, w10 * gx0) TAPH(t101, w10 * gx1)
        TAPH(t110, w11 * gx0) TAPH(t111, w11 * gx1)
#undef TAPH

        float m = mp[p];
        float2 f0 = __half22float2(h0);
        float2 f1 = __half22float2(h1);
        float2 f2 = __half22float2(h2);
        float2 f3 = __half22float2(h3);
        acc[0] = fmaf(m, f0.x, acc[0]); acc[1] = fmaf(m, f0.y, acc[1]);
        acc[2] = fmaf(m, f1.x, acc[2]); acc[3] = fmaf(m, f1.y, acc[3]);
        acc[4] = fmaf(m, f2.x, acc[4]); acc[5] = fmaf(m, f2.y, acc[5]);
        acc[6] = fmaf(m, f3.x, acc[6]); acc[7] = fmaf(m, f3.y, acc[7]);
    }

    int ix = tbx * 4 + lxv, iy = tby * 4 + lyv, iz = tbz * 4 + lzv;
    int v = (iz << 10) + (iy << 5) + ix;
    int cbase = gi * GC + c8 * 8;
#pragma unroll
    for (int e = 0; e < 8; e++)
        g_samp[(cbase + e) * NVOX + v] = acc[e];
}

// ---------------------------------------------------------------------------
// Kernel 5: output GEMM. out[v][oc] = g_samp[c][v]^T @ out_w[c][oc] + out_b.
// ---------------------------------------------------------------------------
__global__ void __launch_bounds__(256)
k_out(const float* __restrict__ out_w, const float* __restrict__ out_b,
      float* __restrict__ out) {
    int vbase = blockIdx.x * 128;
    int tid = threadIdx.x;
    __shared__ float sA[64 * 128];
    __shared__ float sB[64 * 64];

#pragma unroll
    for (int i = 0; i < 4; i++) {
        int lin = i * 1024 + tid * 4;
        *reinterpret_cast<float4*>(&sB[lin]) =
            *reinterpret_cast<const float4*>(&out_w[lin]);
    }
#pragma unroll
    for (int i = 0; i < 8; i++) {
        int lin = i * 1024 + tid * 4;
        int k = lin >> 7, vl = lin & 127;
        *reinterpret_cast<float4*>(&sA[lin]) =
            *reinterpret_cast<const float4*>(&g_samp[k * NVOX + vbase + vl]);
    }
    __syncthreads();

    int tx = tid & 15, ty = tid >> 4;
    float acc[8][4];
#pragma unroll
    for (int i = 0; i < 8; i++)
#pragma unroll
        for (int j = 0; j < 4; j++) acc[i][j] = 0.f;

    const float4* A4 = reinterpret_cast<const float4*>(sA);
    const float4* B4 = reinterpret_cast<const float4*>(sB);
#pragma unroll 8
    for (int k = 0; k < 64; k++) {
        float4 a0 = A4[k * 32 + tx];
        float4 a1 = A4[k * 32 + 16 + tx];
        float4 b  = B4[k * 16 + ty];
        float av[8] = {a0.x, a0.y, a0.z, a0.w, a1.x, a1.y, a1.z, a1.w};
        float bv[4] = {b.x, b.y, b.z, b.w};
#pragma unroll
        for (int i = 0; i < 8; i++)
#pragma unroll
            for (int j = 0; j < 4; j++)
                acc[i][j] = fmaf(av[i], bv[j], acc[i][j]);
    }

    float4 b4 = *reinterpret_cast<const float4*>(&out_b[ty * 4]);
#pragma unroll
    for (int vi = 0; vi < 8; vi++) {
        int v = vbase + ((vi & 4) << 4) + tx * 4 + (vi & 3);
        *reinterpret_cast<float4*>(&out[v * NC + ty * 4]) =
            make_float4(acc[vi][0] + b4.x, acc[vi][1] + b4.y,
                        acc[vi][2] + b4.z, acc[vi][3] + b4.w);
    }
}

// ---------------------------------------------------------------------------
extern "C" void kernel_launch(void* const* d_in, const int* in_sizes, int n_in,
                              void* d_out, int out_size) {
    const float* x      = (const float*)d_in[0];
    const float* dw_w   = (const float*)d_in[1];
    const float* gn_w   = (const float*)d_in[2];
    const float* gn_b   = (const float*)d_in[3];
    const float* inp_w  = (const float*)d_in[4];
    const float* inp_b  = (const float*)d_in[5];
    const float* off_w  = (const float*)d_in[6];
    const float* off_b  = (const float*)d_in[7];
    const float* mask_w = (const float*)d_in[8];
    const float* mask_b = (const float*)d_in[9];
    const float* out_w  = (const float*)d_in[10];
    const float* out_b  = (const float*)d_in[11];
    float* out = (float*)d_out;

    k_init<<<(NC * NJP + 255) / 256, 256>>>(inp_w, off_w, mask_w, inp_b, off_b, mask_b);
    k_dw<<<dim3(32, 64), 256>>>(x, dw_w);
    k_stats<<<1, 1024>>>();
    k_point<<<dim3(NVOX / 128, 5), 256>>>(x, gn_w, gn_b);
    k_samp<<<1024, 256>>>();
    k_out<<<NVOX / 128, 256>>>(out_w, out_b, out);
}